// round 9
// baseline (speedup 1.0000x reference)
#include <cuda_runtime.h>

#define GRID_BLOCKS 2048
#define BLOCK_THREADS 256

__device__ float g_partials[GRID_BLOCKS];
__device__ unsigned int g_done_count = 0;

__global__ __launch_bounds__(BLOCK_THREADS, 8)
void mtnll_fused_kernel(const float* __restrict__ in0,
                        const float* __restrict__ in1,
                        const float* __restrict__ in2,
                        const float* __restrict__ cmap,
                        const int* __restrict__ t0,
                        const int* __restrict__ t1,
                        const int* __restrict__ t2,
                        float* __restrict__ out,
                        int n)
{
    float acc = 0.0f;

    // Block-contiguous tiling: block b owns rows [b*chunk, (b+1)*chunk).
    // chunk = n / GRID_BLOCKS (n = 4194304 -> chunk = 2048 -> exactly 8 iters).
    const int chunk = n / GRID_BLOCKS;
    const int base  = blockIdx.x * chunk;
    const int end   = base + chunk;

    for (int i = base + threadIdx.x; i < end; i += BLOCK_THREADS) {
        const int   a = __ldg(&t0[i]);
        const int   b = __ldg(&t1[i]);
        const int   c = __ldg(&t2[i]);
        const float w = __ldg(&cmap[i]);
        const float p0 = __ldg(&in0[3 * i + a]);
        const float p1 = __ldg(&in1[3 * i + b]);
        const float p2 = __ldg(&in2[3 * i + c]);
        const float s = fmaf(0.5f, p1, fmaf(0.25f, p2, p0));
        acc = fmaf(-w, s, acc);
    }

    // tail rows if n not divisible by GRID_BLOCKS (handled by last block)
    if (blockIdx.x == GRID_BLOCKS - 1) {
        for (int i = GRID_BLOCKS * chunk + threadIdx.x; i < n; i += BLOCK_THREADS) {
            const int   a = __ldg(&t0[i]);
            const int   b = __ldg(&t1[i]);
            const int   c = __ldg(&t2[i]);
            const float w = __ldg(&cmap[i]);
            const float p0 = __ldg(&in0[3 * i + a]);
            const float p1 = __ldg(&in1[3 * i + b]);
            const float p2 = __ldg(&in2[3 * i + c]);
            const float s = fmaf(0.5f, p1, fmaf(0.25f, p2, p0));
            acc = fmaf(-w, s, acc);
        }
    }

    // intra-block reduction
    #pragma unroll
    for (int o = 16; o > 0; o >>= 1)
        acc += __shfl_xor_sync(0xffffffffu, acc, o);

    __shared__ float smem[BLOCK_THREADS / 32];
    const int warp = threadIdx.x >> 5;
    const int lane = threadIdx.x & 31;
    if (lane == 0) smem[warp] = acc;
    __syncthreads();

    __shared__ bool s_is_last;
    if (threadIdx.x == 0) {
        float bsum = 0.0f;
        #pragma unroll
        for (int w = 0; w < BLOCK_THREADS / 32; w++) bsum += smem[w];
        g_partials[blockIdx.x] = bsum;
        __threadfence();
        unsigned int prev = atomicAdd(&g_done_count, 1u);
        s_is_last = (prev == gridDim.x - 1);
    }
    __syncthreads();

    if (s_is_last) {
        const int nb = gridDim.x;
        float v = 0.0f;
        for (int j = threadIdx.x; j < nb; j += BLOCK_THREADS)
            v += g_partials[j];
        #pragma unroll
        for (int o = 16; o > 0; o >>= 1)
            v += __shfl_xor_sync(0xffffffffu, v, o);
        if (lane == 0) smem[warp] = v;
        __syncthreads();
        if (threadIdx.x == 0) {
            float total = 0.0f;
            #pragma unroll
            for (int w = 0; w < BLOCK_THREADS / 32; w++) total += smem[w];
            out[0] = total * (1.0f / (float)n);
            g_done_count = 0;   // reset for next graph replay
        }
    }
}

extern "C" void kernel_launch(void* const* d_in, const int* in_sizes, int n_in,
                              void* d_out, int out_size) {
    const float* in0  = (const float*)d_in[0];
    const float* in1  = (const float*)d_in[1];
    const float* in2  = (const float*)d_in[2];
    const float* cmap = (const float*)d_in[3];
    const int* t0     = (const int*)d_in[4];
    const int* t1     = (const int*)d_in[5];
    const int* t2     = (const int*)d_in[6];
    float* out = (float*)d_out;

    const int n = in_sizes[3];

    mtnll_fused_kernel<<<GRID_BLOCKS, BLOCK_THREADS>>>(
        in0, in1, in2, cmap, t0, t1, t2, out, n);
}